// round 7
// baseline (speedup 1.0000x reference)
#include <cuda_runtime.h>
#include <math.h>
#include <float.h>
#include <stdint.h>

#define NXY    36864      // 192*192 pixels
#define ETL    16
#define NDICT  4000
#define NSLOT  8          // SE (kept) columns; data-driven, padded with -1
#define REC_F  20         // floats per pair record (80 bytes)
#define NH     2          // dictionary halves (cluster size)
#define PAIRS_H 1000      // atom pairs per half
#define PX     2          // pixels per thread
#define TPB    256
#define GRPPX  (TPB * PX) // 512 pixels per group

#define DICT_BYTES (PAIRS_H * REC_F * 4)       // 80000
#define MBOX_OFF   DICT_BYTES                  // 8-aligned
#define SMEM_TOTAL (DICT_BYTES + GRPPX * 8)    // + u64 mailbox = 84096

// ---- packed f32x2 helpers (Blackwell FFMA2 path) ------------------------
#define FMA_F32X2(d, a, b, c) \
    asm("fma.rn.f32x2 %0, %1, %2, %3;" : "=l"(d) : "l"(a), "l"(b), "l"(c))
#define PACK_F32X2(out, lo, hi) \
    asm("mov.b64 %0, {%1, %2};" : "=l"(out) : "f"(lo), "f"(hi))
#define UNPACK_F32X2(lo, hi, in) \
    asm("mov.b64 {%0, %1}, %2;" : "=f"(lo), "=f"(hi) : "l"(in))

__device__ __forceinline__ uint32_t smem_u32(const void* p) {
    uint32_t a;
    asm("{ .reg .u64 t; cvta.to.shared.u64 t, %1; cvt.u32.u64 %0, t; }"
        : "=r"(a) : "l"(p));
    return a;
}
__device__ __forceinline__ uint32_t my_ctarank() {
    uint32_t r;
    asm("mov.u32 %0, %%cluster_ctarank;" : "=r"(r));
    return r;
}
__device__ __forceinline__ void remote_st_u64(uint32_t local_addr,
                                              uint32_t rank,
                                              unsigned long long v) {
    uint32_t ra;
    asm volatile("mapa.shared::cluster.u32 %0, %1, %2;"
                 : "=r"(ra) : "r"(local_addr), "r"(rank));
    asm volatile("st.shared::cluster.u64 [%0], %1;" :: "r"(ra), "l"(v)
                 : "memory");
}
#define CLUSTER_SYNC() do { \
    asm volatile("barrier.cluster.arrive.aligned;" ::: "memory"); \
    asm volatile("barrier.cluster.wait.aligned;"   ::: "memory"); \
} while (0)

__device__ __forceinline__ void get_cols(const float* __restrict__ delta_ms,
                                         int* cols) {
    int j = 0;
    for (int k = 0; k < ETL; k++) {
        if (delta_ms[k] * 1e-3f < 1e-3f && j < NSLOT) cols[j++] = k;
    }
    for (; j < NSLOT; j++) cols[j] = -1;
}

// order-isomorphic uint32 for float compare
__device__ __forceinline__ unsigned int fmono(float f) {
    unsigned int u = __float_as_uint(f);
    return (u & 0x80000000u) ? ~u : (u | 0x80000000u);
}
__device__ __forceinline__ float fmono_inv(unsigned int u) {
    return (u & 0x80000000u) ? __uint_as_float(u ^ 0x80000000u)
                             : __uint_as_float(~u);
}

// scores of one 80-B record (2 atoms); bit-deterministic FMA chain
__device__ __forceinline__ void rec_scores(const char* rec,
                                           const uint64_t* sp,
                                           float& lo, float& hi) {
    const ulonglong2* r = (const ulonglong2*)rec;
    ulonglong2 q0 = r[0];
    ulonglong2 q1 = r[1];
    ulonglong2 q2 = r[2];
    ulonglong2 q3 = r[3];
    uint64_t acc = *(const unsigned long long*)(rec + 64);
    FMA_F32X2(acc, q0.x, sp[0], acc);
    FMA_F32X2(acc, q0.y, sp[1], acc);
    FMA_F32X2(acc, q1.x, sp[2], acc);
    FMA_F32X2(acc, q1.y, sp[3], acc);
    FMA_F32X2(acc, q2.x, sp[4], acc);
    FMA_F32X2(acc, q2.y, sp[5], acc);
    FMA_F32X2(acc, q3.x, sp[6], acc);
    FMA_F32X2(acc, q3.y, sp[7], acc);
    UNPACK_F32X2(lo, hi, acc);
}

// ---------------------------------------------------------------------------
// Single fused kernel. grid = 72 pixel-groups x 2 dict-halves, clusters of 2.
// Each CTA: builds its dict half in SMEM, scans it for 512 pixels (2/thread),
// then cluster-merges the per-half winners via DSMEM; rank 0 writes outputs.
// ---------------------------------------------------------------------------
__global__ void __launch_bounds__(TPB, 1) __cluster_dims__(NH, 1, 1)
match_kernel(const float* __restrict__ sig,       // [NXY, ETL]
             const float* __restrict__ db_mag,    // [NDICT, ETL]
             const float* __restrict__ t2s,       // [NDICT]
             const float* __restrict__ b1s,       // [NDICT]
             const float* __restrict__ delta_ms,  // [ETL]
             float* __restrict__ out)              // [3*NXY]
{
    extern __shared__ __align__(16) char smraw[];
    float* sdict = (float*)smraw;                               // 80 KB
    unsigned long long* mbox =
        (unsigned long long*)(smraw + MBOX_OFF);                // 4 KB

    const int group = blockIdx.x >> 1;   // 0..71 pixel group
    const int q     = blockIdx.x & 1;    // dict half (== cluster rank)

    int cols[NSLOT];
    get_cols(delta_ms, cols);

    // ---- Stage this half's packed records (normalization == reference) ----
    for (int a = threadIdx.x; a < 2 * PAIRS_H; a += TPB) {
        int ga = q * (2 * PAIRS_H) + a;   // global atom index
        float v[NSLOT];
        float n2 = 0.0f;
#pragma unroll
        for (int j = 0; j < NSLOT; j++) {
            int c = cols[j];
            float x = (c >= 0) ? db_mag[ga * ETL + c] : 0.0f;
            v[j] = x;
            n2 = fmaf(x, x, n2);
        }
        float inv = 0.0f;
        if (n2 > 0.0f) {
            float r = 1.0f / sqrtf(n2);
            if (isfinite(r)) inv = r;
        }
        float* rec = sdict + (a >> 1) * REC_F;
        int par = a & 1;
        float d2 = 0.0f;
#pragma unroll
        for (int j = 0; j < NSLOT; j++) {
            float s = v[j] * inv;
            rec[2 * j + par] = 2.0f * s;      // w = 2 * normalized value
            d2 = fmaf(s, s, d2);
        }
        rec[16 + par] = -d2;                   // bias
    }

    // ---- Load + normalize this thread's pixels (nan_to_num semantics) ----
    int n[PX];
    float s2[PX];
    uint64_t sp[PX][NSLOT];
#pragma unroll
    for (int u = 0; u < PX; u++) {
        n[u] = group * GRPPX + u * TPB + threadIdx.x;
        float m[NSLOT];
        float nm2 = 0.0f;
#pragma unroll
        for (int j = 0; j < NSLOT; j++) {
            int c = cols[j];
            float v = (c >= 0) ? sig[n[u] * ETL + c] : 0.0f;
            m[j] = v;
            nm2 = fmaf(v, v, nm2);
        }
        float inv = 0.0f;
        if (nm2 > 0.0f) {
            float r = 1.0f / sqrtf(nm2);
            if (isfinite(r)) inv = r;
        }
        float acc = 0.0f;
#pragma unroll
        for (int j = 0; j < NSLOT; j++) {
            float s = m[j] * inv;
            acc = fmaf(s, s, acc);
            PACK_F32X2(sp[u][j], s, s);
        }
        s2[u] = acc;
    }

    __syncthreads();

    // ---- Scan: 500 iterations x (2 records = 4 atoms) x PX pixels ----
    float best[PX];
    int bit[PX];
#pragma unroll
    for (int u = 0; u < PX; u++) { best[u] = -FLT_MAX; bit[u] = 0; }

    const char* base = (const char*)sdict;
#pragma unroll 2
    for (int i = 0; i < PAIRS_H / 2; i++) {
        const char* r0 = base + (2 * i) * 80;
        const char* r1 = r0 + 80;
#pragma unroll
        for (int u = 0; u < PX; u++) {
            float a0, a1, a2, a3;
            rec_scores(r0, sp[u], a0, a1);
            rec_scores(r1, sp[u], a2, a3);
            float m = fmaxf(fmaxf(a0, a1), fmaxf(a2, a3));
            if (m > best[u]) { best[u] = m; bit[u] = i; }  // first iter wins
        }
    }

    // ---- Deterministic winner recompute -> merge key ----
    unsigned long long key[PX];
#pragma unroll
    for (int u = 0; u < PX; u++) {
        int i = bit[u];
        const char* r0 = base + (2 * i) * 80;
        const char* r1 = r0 + 80;
        float a0, a1, a2, a3;
        rec_scores(r0, sp[u], a0, a1);
        rec_scores(r1, sp[u], a2, a3);
        int j = (a0 == best[u]) ? 0 : (a1 == best[u]) ? 1
              : (a2 == best[u]) ? 2 : 3;
        int atom = q * (2 * PAIRS_H) + 4 * i + j;
        key[u] = ((unsigned long long)fmono(best[u]) << 32)
               | (unsigned long long)(65535 - atom);
    }

    // ---- Cluster merge: rank 1 pushes keys to rank 0's mailbox ----
    uint32_t rank = my_ctarank();
    if (rank == 1) {
#pragma unroll
        for (int u = 0; u < PX; u++) {
            uint32_t la = smem_u32(&mbox[u * TPB + threadIdx.x]);
            remote_st_u64(la, 0, key[u]);
        }
    }
    CLUSTER_SYNC();

    if (rank == 0) {
#pragma unroll
        for (int u = 0; u < PX; u++) {
            unsigned long long other = mbox[u * TPB + threadIdx.x];
            unsigned long long merged = (other > key[u]) ? other : key[u];
            int atom = 65535 - (int)(merged & 0xFFFFULL);
            float score = fmono_inv((unsigned int)(merged >> 32));
            float dist2 = fmaxf(s2[u] - score, 0.0f);
            out[n[u]]           = t2s[atom];
            out[NXY + n[u]]     = b1s[atom];
            out[2 * NXY + n[u]] = sqrtf(dist2);
        }
    }
}

// ---------------------------------------------------------------------------
extern "C" void kernel_launch(void* const* d_in, const int* in_sizes, int n_in,
                              void* d_out, int out_size) {
    const float* slice_signal = (const float*)d_in[0];  // [192,192,16]
    const float* db_mag       = (const float*)d_in[1];  // [4000,16]
    const float* db_t2s_s     = (const float*)d_in[2];  // [4000]
    const float* db_b1s       = (const float*)d_in[3];  // [4000]
    const float* delta_ms     = (const float*)d_in[4];  // [16]
    float* out = (float*)d_out;

    cudaFuncSetAttribute(match_kernel,
                         cudaFuncAttributeMaxDynamicSharedMemorySize,
                         SMEM_TOTAL);

    // 72 pixel groups x 2 dict halves = 144 CTAs = 72 clusters of 2 (1 wave)
    match_kernel<<<(NXY / GRPPX) * NH, TPB, SMEM_TOTAL>>>(
        slice_signal, db_mag, db_t2s_s, db_b1s, delta_ms, out);
}

// round 8
// speedup vs baseline: 1.0505x; 1.0505x over previous
#include <cuda_runtime.h>
#include <math.h>
#include <float.h>
#include <stdint.h>

#define NXY    36864      // 192*192 pixels
#define ETL    16
#define NDICT  4000
#define NSLOT  8          // SE (kept) columns; data-driven, padded with -1
#define REC_F  20         // floats per pair record (80 bytes)
#define NQ     4          // dictionary quarters
#define PAIRS_Q 500       // atom pairs per quarter
#define ATOMS_Q (2 * PAIRS_Q)
#define PX     2          // pixels per thread
#define TPB    256
#define GRPPX  (TPB * PX) // 512 pixels per group
#define NGRP   (NXY / GRPPX)  // 72 pixel groups

#define DICT_BYTES (PAIRS_Q * REC_F * 4)   // 40000 bytes per CTA

// Per-quarter partial results: key = monotone(score)<<32 | (65535 - atom).
// Every slot is written by exactly one CTA every launch -> no zeroing, no atomics.
__device__ unsigned long long g_part[NQ * NXY];

// ---- packed f32x2 helpers (Blackwell FFMA2 path) ------------------------
#define FMA_F32X2(d, a, b, c) \
    asm("fma.rn.f32x2 %0, %1, %2, %3;" : "=l"(d) : "l"(a), "l"(b), "l"(c))
#define PACK_F32X2(out, lo, hi) \
    asm("mov.b64 %0, {%1, %2};" : "=l"(out) : "f"(lo), "f"(hi))
#define UNPACK_F32X2(lo, hi, in) \
    asm("mov.b64 {%0, %1}, %2;" : "=f"(lo), "=f"(hi) : "l"(in))

__device__ __forceinline__ void get_cols(const float* __restrict__ delta_ms,
                                         int* cols) {
    int j = 0;
    for (int k = 0; k < ETL; k++) {
        if (delta_ms[k] * 1e-3f < 1e-3f && j < NSLOT) cols[j++] = k;
    }
    for (; j < NSLOT; j++) cols[j] = -1;
}

// order-isomorphic uint32 for float compare
__device__ __forceinline__ unsigned int fmono(float f) {
    unsigned int u = __float_as_uint(f);
    return (u & 0x80000000u) ? ~u : (u | 0x80000000u);
}
__device__ __forceinline__ float fmono_inv(unsigned int u) {
    return (u & 0x80000000u) ? __uint_as_float(u ^ 0x80000000u)
                             : __uint_as_float(~u);
}

// scores of one 80-B record (2 atoms); bit-deterministic FMA chain
__device__ __forceinline__ void rec_scores(const char* rec,
                                           const uint64_t* sp,
                                           float& lo, float& hi) {
    const ulonglong2* r = (const ulonglong2*)rec;
    ulonglong2 q0 = r[0];
    ulonglong2 q1 = r[1];
    ulonglong2 q2 = r[2];
    ulonglong2 q3 = r[3];
    uint64_t acc = *(const unsigned long long*)(rec + 64);
    FMA_F32X2(acc, q0.x, sp[0], acc);
    FMA_F32X2(acc, q0.y, sp[1], acc);
    FMA_F32X2(acc, q1.x, sp[2], acc);
    FMA_F32X2(acc, q1.y, sp[3], acc);
    FMA_F32X2(acc, q2.x, sp[4], acc);
    FMA_F32X2(acc, q2.y, sp[5], acc);
    FMA_F32X2(acc, q3.x, sp[6], acc);
    FMA_F32X2(acc, q3.y, sp[7], acc);
    UNPACK_F32X2(lo, hi, acc);
}

// ---------------------------------------------------------------------------
// Kernel 1: match. grid = 72 pixel-groups x 4 dict-quarters = 288 CTAs,
// 2 CTAs/SM (40 KB SMEM each). Each CTA builds its dict quarter in SMEM,
// scans 125 iterations x 8 atoms for 512 pixels (2/thread), writes per-pixel
// winner keys to its g_part slice (plain stores, race-free).
// ---------------------------------------------------------------------------
__global__ void __launch_bounds__(TPB, 2) match_kernel(
    const float* __restrict__ sig,       // [NXY, ETL]
    const float* __restrict__ db_mag,    // [NDICT, ETL]
    const float* __restrict__ delta_ms)  // [ETL]
{
    extern __shared__ __align__(16) float sdict[];   // 40 KB

    const int group = blockIdx.x >> 2;   // 0..71
    const int q     = blockIdx.x & 3;    // dict quarter

    int cols[NSLOT];
    get_cols(delta_ms, cols);

    // ---- Build this quarter's packed records (normalization == reference) ----
    for (int a = threadIdx.x; a < ATOMS_Q; a += TPB) {
        int ga = q * ATOMS_Q + a;        // global atom index
        float v[NSLOT];
        float n2 = 0.0f;
#pragma unroll
        for (int j = 0; j < NSLOT; j++) {
            int c = cols[j];
            float x = (c >= 0) ? db_mag[ga * ETL + c] : 0.0f;
            v[j] = x;
            n2 = fmaf(x, x, n2);
        }
        float inv = 0.0f;
        if (n2 > 0.0f) {
            float r = 1.0f / sqrtf(n2);
            if (isfinite(r)) inv = r;
        }
        float* rec = sdict + (a >> 1) * REC_F;
        int par = a & 1;
        float d2 = 0.0f;
#pragma unroll
        for (int j = 0; j < NSLOT; j++) {
            float s = v[j] * inv;
            rec[2 * j + par] = 2.0f * s;     // w = 2 * normalized value
            d2 = fmaf(s, s, d2);
        }
        rec[16 + par] = -d2;                  // bias
        if (par == 0) { rec[18] = 0.0f; rec[19] = 0.0f; }
    }

    // ---- Load + normalize this thread's pixels (nan_to_num semantics) ----
    int n[PX];
    uint64_t sp[PX][NSLOT];
#pragma unroll
    for (int u = 0; u < PX; u++) {
        n[u] = group * GRPPX + u * TPB + threadIdx.x;
        float m[NSLOT];
        float nm2 = 0.0f;
#pragma unroll
        for (int j = 0; j < NSLOT; j++) {
            int c = cols[j];
            float v = (c >= 0) ? sig[n[u] * ETL + c] : 0.0f;
            m[j] = v;
            nm2 = fmaf(v, v, nm2);
        }
        float inv = 0.0f;
        if (nm2 > 0.0f) {
            float r = 1.0f / sqrtf(nm2);
            if (isfinite(r)) inv = r;
        }
#pragma unroll
        for (int j = 0; j < NSLOT; j++) {
            float s = m[j] * inv;
            PACK_F32X2(sp[u][j], s, s);
        }
    }

    __syncthreads();

    // ---- Scan: 125 iterations x (4 records = 8 atoms) x PX pixels ----
    float best[PX];
    int bit[PX];
#pragma unroll
    for (int u = 0; u < PX; u++) { best[u] = -FLT_MAX; bit[u] = 0; }

    const char* base = (const char*)sdict;
#pragma unroll 1
    for (int i = 0; i < PAIRS_Q / 4; i++) {
        const char* r0 = base + (size_t)(4 * i) * 80;
#pragma unroll
        for (int u = 0; u < PX; u++) {
            float a0, a1, a2, a3, a4, a5, a6, a7;
            rec_scores(r0,       sp[u], a0, a1);
            rec_scores(r0 + 80,  sp[u], a2, a3);
            rec_scores(r0 + 160, sp[u], a4, a5);
            rec_scores(r0 + 240, sp[u], a6, a7);
            float m01 = fmaxf(a0, a1), m23 = fmaxf(a2, a3);
            float m45 = fmaxf(a4, a5), m67 = fmaxf(a6, a7);
            float m = fmaxf(fmaxf(m01, m23), fmaxf(m45, m67));
            if (m > best[u]) { best[u] = m; bit[u] = i; }  // first iter wins
        }
    }

    // ---- Deterministic winner recompute -> write partial key ----
#pragma unroll
    for (int u = 0; u < PX; u++) {
        int i = bit[u];
        const char* r0 = base + (size_t)(4 * i) * 80;
        float a[8];
        rec_scores(r0,       sp[u], a[0], a[1]);
        rec_scores(r0 + 80,  sp[u], a[2], a[3]);
        rec_scores(r0 + 160, sp[u], a[4], a[5]);
        rec_scores(r0 + 240, sp[u], a[6], a[7]);
        int j = 7;
#pragma unroll
        for (int k = 6; k >= 0; k--) if (a[k] == best[u]) j = k;
        int atom = q * ATOMS_Q + 8 * i + j;
        unsigned long long key =
            ((unsigned long long)fmono(best[u]) << 32)
            | (unsigned long long)(65535 - atom);
        g_part[q * NXY + n[u]] = key;
    }
}

// ---------------------------------------------------------------------------
// Kernel 2: finalize — merge the 4 quarter keys, recompute s2, write outputs.
// ---------------------------------------------------------------------------
__global__ void finalize_kernel(const float* __restrict__ sig,
                                const float* __restrict__ t2s,
                                const float* __restrict__ b1s,
                                const float* __restrict__ delta_ms,
                                float* __restrict__ out) {
    int n = blockIdx.x * blockDim.x + threadIdx.x;
    if (n >= NXY) return;

    int cols[NSLOT];
    get_cols(delta_ms, cols);

    float nm2 = 0.0f;
    float m[NSLOT];
#pragma unroll
    for (int j = 0; j < NSLOT; j++) {
        int c = cols[j];
        float v = (c >= 0) ? sig[n * ETL + c] : 0.0f;
        m[j] = v;
        nm2 = fmaf(v, v, nm2);
    }
    float inv = 0.0f;
    if (nm2 > 0.0f) {
        float r = 1.0f / sqrtf(nm2);
        if (isfinite(r)) inv = r;
    }
    float s2 = 0.0f;
#pragma unroll
    for (int j = 0; j < NSLOT; j++) {
        float s = m[j] * inv;
        s2 = fmaf(s, s, s2);
    }

    unsigned long long key = g_part[n];
#pragma unroll
    for (int qq = 1; qq < NQ; qq++) {
        unsigned long long k2 = g_part[qq * NXY + n];
        if (k2 > key) key = k2;   // ties: lower atom index already wins in key
    }
    int atom = 65535 - (int)(key & 0xFFFFULL);
    float score = fmono_inv((unsigned int)(key >> 32));
    float dist2 = fmaxf(s2 - score, 0.0f);

    out[n]           = t2s[atom];
    out[NXY + n]     = b1s[atom];
    out[2 * NXY + n] = sqrtf(dist2);
}

// ---------------------------------------------------------------------------
extern "C" void kernel_launch(void* const* d_in, const int* in_sizes, int n_in,
                              void* d_out, int out_size) {
    const float* slice_signal = (const float*)d_in[0];  // [192,192,16]
    const float* db_mag       = (const float*)d_in[1];  // [4000,16]
    const float* db_t2s_s     = (const float*)d_in[2];  // [4000]
    const float* db_b1s       = (const float*)d_in[3];  // [4000]
    const float* delta_ms     = (const float*)d_in[4];  // [16]
    float* out = (float*)d_out;

    cudaFuncSetAttribute(match_kernel,
                         cudaFuncAttributeMaxDynamicSharedMemorySize,
                         DICT_BYTES);

    match_kernel<<<NGRP * NQ, TPB, DICT_BYTES>>>(slice_signal, db_mag,
                                                 delta_ms);
    finalize_kernel<<<(NXY + 255) / 256, 256>>>(slice_signal, db_t2s_s,
                                                db_b1s, delta_ms, out);
}

// round 9
// speedup vs baseline: 1.1550x; 1.0995x over previous
#include <cuda_runtime.h>
#include <math.h>
#include <float.h>
#include <stdint.h>

#define NXY     36864      // 192*192 pixels
#define ETL     16
#define NDICT   4000
#define NSLOT   8          // SE (kept) columns; data-driven, padded with -1
#define REC_F   20         // floats per pair record (80 bytes)
#define NQ      8          // dictionary slices
#define PAIRS_S 250        // atom pairs per slice
#define ATOMS_S (2 * PAIRS_S)   // 500
#define PX      4          // pixels per thread
#define TPB     256
#define GRPPX   (TPB * PX)      // 1024 pixels per group
#define NGRP    (NXY / GRPPX)   // 36 pixel groups

// Per-slice partial results: key = monotone(score)<<32 | (65535 - atom).
// Every slot written exactly once per launch -> no zeroing, no atomic-max.
__device__ unsigned long long g_part[NQ * NXY];
// Arrival counters (one per pixel group). Zero at module load; atomicInc
// wraps back to 0 after NQ arrivals -> self-resetting across graph replays.
__device__ unsigned int g_cnt[NGRP];

// ---- packed f32x2 helpers (Blackwell FFMA2 path) ------------------------
#define FMA_F32X2(d, a, b, c) \
    asm("fma.rn.f32x2 %0, %1, %2, %3;" : "=l"(d) : "l"(a), "l"(b), "l"(c))
#define PACK_F32X2(out, lo, hi) \
    asm("mov.b64 %0, {%1, %2};" : "=l"(out) : "f"(lo), "f"(hi))
#define UNPACK_F32X2(lo, hi, in) \
    asm("mov.b64 {%0, %1}, %2;" : "=f"(lo), "=f"(hi) : "l"(in))

__device__ __forceinline__ void get_cols(const float* __restrict__ delta_ms,
                                         int* cols) {
    int j = 0;
    for (int k = 0; k < ETL; k++) {
        if (delta_ms[k] * 1e-3f < 1e-3f && j < NSLOT) cols[j++] = k;
    }
    for (; j < NSLOT; j++) cols[j] = -1;
}

// order-isomorphic uint32 for float compare
__device__ __forceinline__ unsigned int fmono(float f) {
    unsigned int u = __float_as_uint(f);
    return (u & 0x80000000u) ? ~u : (u | 0x80000000u);
}
__device__ __forceinline__ float fmono_inv(unsigned int u) {
    return (u & 0x80000000u) ? __uint_as_float(u ^ 0x80000000u)
                             : __uint_as_float(~u);
}

// Preloaded record pair (2 records = 4 atoms), register-resident.
struct RecPair {
    ulonglong2 q0a, q1a, q2a, q3a;  uint64_t ba;   // record 0
    ulonglong2 q0b, q1b, q2b, q3b;  uint64_t bb;   // record 1
};

__device__ __forceinline__ void load_recpair(const char* r0, RecPair& rp) {
    const ulonglong2* a = (const ulonglong2*)r0;
    rp.q0a = a[0]; rp.q1a = a[1]; rp.q2a = a[2]; rp.q3a = a[3];
    rp.ba  = *(const unsigned long long*)(r0 + 64);
    const ulonglong2* b = (const ulonglong2*)(r0 + 80);
    rp.q0b = b[0]; rp.q1b = b[1]; rp.q2b = b[2]; rp.q3b = b[3];
    rp.bb  = *(const unsigned long long*)(r0 + 144);
}

// 4 scores (2 records x 2 atoms) from register-resident records;
// bit-deterministic FMA chain order.
__device__ __forceinline__ void pair_scores(const RecPair& rp,
                                            const uint64_t* sp,
                                            float& s0, float& s1,
                                            float& s2, float& s3) {
    uint64_t acc = rp.ba;
    FMA_F32X2(acc, rp.q0a.x, sp[0], acc);
    FMA_F32X2(acc, rp.q0a.y, sp[1], acc);
    FMA_F32X2(acc, rp.q1a.x, sp[2], acc);
    FMA_F32X2(acc, rp.q1a.y, sp[3], acc);
    FMA_F32X2(acc, rp.q2a.x, sp[4], acc);
    FMA_F32X2(acc, rp.q2a.y, sp[5], acc);
    FMA_F32X2(acc, rp.q3a.x, sp[6], acc);
    FMA_F32X2(acc, rp.q3a.y, sp[7], acc);
    uint64_t acc2 = rp.bb;
    FMA_F32X2(acc2, rp.q0b.x, sp[0], acc2);
    FMA_F32X2(acc2, rp.q0b.y, sp[1], acc2);
    FMA_F32X2(acc2, rp.q1b.x, sp[2], acc2);
    FMA_F32X2(acc2, rp.q1b.y, sp[3], acc2);
    FMA_F32X2(acc2, rp.q2b.x, sp[4], acc2);
    FMA_F32X2(acc2, rp.q2b.y, sp[5], acc2);
    FMA_F32X2(acc2, rp.q3b.x, sp[6], acc2);
    FMA_F32X2(acc2, rp.q3b.y, sp[7], acc2);
    UNPACK_F32X2(s0, s1, acc);
    UNPACK_F32X2(s2, s3, acc2);
}

// ---------------------------------------------------------------------------
// Single fused kernel. grid = 36 pixel-groups x 8 dict-slices = 288 CTAs,
// 2 CTAs/SM (20 KB static SMEM). Each CTA builds its slice, scans it for
// 1024 pixels (4/thread), writes partial keys; the LAST CTA of each group
// (atomicInc wrap) merges all 8 partials and writes the outputs.
// ---------------------------------------------------------------------------
__global__ void __launch_bounds__(TPB, 2) fused_kernel(
    const float* __restrict__ sig,       // [NXY, ETL]
    const float* __restrict__ db_mag,    // [NDICT, ETL]
    const float* __restrict__ t2s,       // [NDICT]
    const float* __restrict__ b1s,       // [NDICT]
    const float* __restrict__ delta_ms,  // [ETL]
    float* __restrict__ out)             // [3*NXY]: t2 | b1 | min_dist
{
    __shared__ __align__(16) float sdict[PAIRS_S * REC_F];   // 20 KB
    __shared__ int s_last;

    const int group = blockIdx.x >> 3;   // 0..35
    const int q     = blockIdx.x & 7;    // dict slice

    int cols[NSLOT];
    get_cols(delta_ms, cols);

    // ---- Build this slice's packed records (normalization == reference) ----
    for (int a = threadIdx.x; a < ATOMS_S; a += TPB) {
        int ga = q * ATOMS_S + a;        // global atom index
        float v[NSLOT];
        float n2 = 0.0f;
#pragma unroll
        for (int j = 0; j < NSLOT; j++) {
            int c = cols[j];
            float x = (c >= 0) ? db_mag[ga * ETL + c] : 0.0f;
            v[j] = x;
            n2 = fmaf(x, x, n2);
        }
        float inv = 0.0f;
        if (n2 > 0.0f) {
            float r = 1.0f / sqrtf(n2);
            if (isfinite(r)) inv = r;
        }
        float* rec = sdict + (a >> 1) * REC_F;
        int par = a & 1;
        float d2 = 0.0f;
#pragma unroll
        for (int j = 0; j < NSLOT; j++) {
            float s = v[j] * inv;
            rec[2 * j + par] = 2.0f * s;     // w = 2 * normalized value
            d2 = fmaf(s, s, d2);
        }
        rec[16 + par] = -d2;                  // bias
    }

    // ---- Load + normalize this thread's 4 pixels (nan_to_num semantics) ----
    int n[PX];
    float s2px[PX];
    uint64_t sp[PX][NSLOT];
#pragma unroll
    for (int u = 0; u < PX; u++) {
        n[u] = group * GRPPX + u * TPB + threadIdx.x;
        float m[NSLOT];
        float nm2 = 0.0f;
#pragma unroll
        for (int j = 0; j < NSLOT; j++) {
            int c = cols[j];
            float v = (c >= 0) ? sig[n[u] * ETL + c] : 0.0f;
            m[j] = v;
            nm2 = fmaf(v, v, nm2);
        }
        float inv = 0.0f;
        if (nm2 > 0.0f) {
            float r = 1.0f / sqrtf(nm2);
            if (isfinite(r)) inv = r;
        }
        float acc = 0.0f;
#pragma unroll
        for (int j = 0; j < NSLOT; j++) {
            float s = m[j] * inv;
            acc = fmaf(s, s, acc);
            PACK_F32X2(sp[u][j], s, s);
        }
        s2px[u] = acc;
    }

    __syncthreads();

    // ---- Scan: 125 iterations x (2 records = 4 atoms) x 4 pixels ----
    float best[PX];
    int bit[PX];
#pragma unroll
    for (int u = 0; u < PX; u++) { best[u] = -FLT_MAX; bit[u] = 0; }

    const char* base = (const char*)sdict;
#pragma unroll 1
    for (int i = 0; i < PAIRS_S / 2; i++) {
        RecPair rp;
        load_recpair(base + (size_t)(2 * i) * 80, rp);   // 10 LDS, once
#pragma unroll
        for (int u = 0; u < PX; u++) {
            float a0, a1, a2, a3;
            pair_scores(rp, sp[u], a0, a1, a2, a3);
            float m = fmaxf(fmaxf(a0, a1), fmaxf(a2, a3));
            if (m > best[u]) { best[u] = m; bit[u] = i; }  // first iter wins
        }
    }

    // ---- Deterministic winner recompute -> write partial key ----
    unsigned long long mykey[PX];
#pragma unroll
    for (int u = 0; u < PX; u++) {
        RecPair rp;
        load_recpair(base + (size_t)(2 * bit[u]) * 80, rp);
        float a0, a1, a2, a3;
        pair_scores(rp, sp[u], a0, a1, a2, a3);
        int j = (a0 == best[u]) ? 0 : (a1 == best[u]) ? 1
              : (a2 == best[u]) ? 2 : 3;
        int atom = q * ATOMS_S + 4 * bit[u] + j;
        mykey[u] = ((unsigned long long)fmono(best[u]) << 32)
                 | (unsigned long long)(65535 - atom);
        g_part[q * NXY + n[u]] = mykey[u];
    }

    // ---- Arrival: last CTA of this pixel group merges ----
    __threadfence();          // publish partial keys (release)
    __syncthreads();          // all warps' stores + fences done
    if (threadIdx.x == 0) {
        unsigned int old = atomicInc(&g_cnt[group], NQ - 1);  // wraps to 0
        s_last = (old == NQ - 1);
    }
    __syncthreads();
    if (!s_last) return;

    __threadfence();          // acquire: see all slices' partial keys
#pragma unroll
    for (int u = 0; u < PX; u++) {
        unsigned long long key = mykey[u];
#pragma unroll
        for (int qq = 0; qq < NQ; qq++) {
            unsigned long long k2 = g_part[qq * NXY + n[u]];
            if (k2 > key) key = k2;   // ties: lower atom already wins in key
        }
        int atom = 65535 - (int)(key & 0xFFFFULL);
        float score = fmono_inv((unsigned int)(key >> 32));
        float dist2 = fmaxf(s2px[u] - score, 0.0f);
        out[n[u]]           = t2s[atom];
        out[NXY + n[u]]     = b1s[atom];
        out[2 * NXY + n[u]] = sqrtf(dist2);
    }
}

// ---------------------------------------------------------------------------
extern "C" void kernel_launch(void* const* d_in, const int* in_sizes, int n_in,
                              void* d_out, int out_size) {
    const float* slice_signal = (const float*)d_in[0];  // [192,192,16]
    const float* db_mag       = (const float*)d_in[1];  // [4000,16]
    const float* db_t2s_s     = (const float*)d_in[2];  // [4000]
    const float* db_b1s       = (const float*)d_in[3];  // [4000]
    const float* delta_ms     = (const float*)d_in[4];  // [16]
    float* out = (float*)d_out;

    fused_kernel<<<NGRP * NQ, TPB>>>(slice_signal, db_mag, db_t2s_s,
                                     db_b1s, delta_ms, out);
}